// round 11
// baseline (speedup 1.0000x reference)
#include <cuda_runtime.h>
#include <cuda_fp16.h>
#include <cstdint>

// Problem dims
#define BB 64
#define RR 50
#define LL 15
#define DD 1024
#define FF 4096

// GEMM: M=B*R=3200, N=D=1024, K=F=4096
#define GM 3200
#define GN 1024
#define GK 4096

// Stream-K persistent GEMM: 148 CTAs, tile 128x128, BK=64.
#define BM 128
#define BN 128
#define BK 64
#define NTILE_N (GN / BN)            // 8
#define NTILE (GM / BM * NTILE_N)    // 200
#define ITPT (GK / BK)               // 64 iters per tile
#define TOTAL_IT (NTILE * ITPT)      // 12800
#define NCTA 148
#define SEGMAX 3

#define APH 72                       // padded row stride in halves (144B)
#define STAGES 4
#define A_STAGE_BYTES (BM * APH * 2)          // 18432
#define STAGE_BYTES (2 * BM * APH * 2)        // 36864
#define SMEM_TOTAL (STAGES * STAGE_BYTES)     // 147456
#define NTHREADS 256

// pooling fused: 148 CTAs x 22 rows (last CTAs partial), 4 steps/iter
#define PROWS 22
#define PGROUP 4

// fp16(rna) copies; stream-K partial scratch; 1/len
__device__ __half g_Ah[GM * GK];
__device__ __half g_Wh[GN * GK];
__device__ float g_scr[NCTA * SEGMAX * BM * BN];   // 29 MB
__device__ float g_invlen[GM];

__device__ __forceinline__ int ctastart(int c) {
    return (int)(((long long)c * TOTAL_IT) / NCTA);
}
__device__ __forceinline__ int cta_of(int g) {
    int c = (int)(((long long)g * NCTA) / TOTAL_IT);
    while (ctastart(c + 1) <= g) ++c;
    while (ctastart(c) > g) --c;
    return c;
}

__device__ __forceinline__ void mma_f16(float& c0, float& c1, float& c2, float& c3,
                                        uint32_t a0, uint32_t a1, uint32_t a2, uint32_t a3,
                                        uint32_t b0, uint32_t b1) {
    asm volatile(
        "mma.sync.aligned.m16n8k16.row.col.f32.f16.f16.f32 "
        "{%0,%1,%2,%3}, {%4,%5,%6,%7}, {%8,%9}, {%0,%1,%2,%3};\n"
        : "+f"(c0), "+f"(c1), "+f"(c2), "+f"(c3)
        : "r"(a0), "r"(a1), "r"(a2), "r"(a3), "r"(b0), "r"(b1));
}

__device__ __forceinline__ uint32_t smem_u32(const void* p) {
    uint32_t a;
    asm("{ .reg .u64 t; cvta.to.shared.u64 t, %1; cvt.u32.u64 %0, t; }" : "=r"(a) : "l"(p));
    return a;
}

#define CP_ASYNC16(dst, src) \
    asm volatile("cp.async.cg.shared.global [%0], [%1], 16;" :: "r"(dst), "l"(src) : "memory")
#define CP_COMMIT() asm volatile("cp.async.commit_group;" ::: "memory")
#define CP_WAIT(n) asm volatile("cp.async.wait_group %0;" :: "n"(n) : "memory")

#define LDSM4(r0, r1, r2, r3, addr) \
    asm volatile("ldmatrix.sync.aligned.m8n8.x4.shared.b16 {%0,%1,%2,%3}, [%4];" \
                 : "=r"(r0), "=r"(r1), "=r"(r2), "=r"(r3) : "r"(addr))

// ─────────────────── prepass: fp32 -> fp16(rna), plus 1/len ───────────────────
__global__ void __launch_bounds__(256)
cvt_f16_kernel(const float* __restrict__ A, const float* __restrict__ W,
               const int* __restrict__ lens) {
    const int gid = blockIdx.x * blockDim.x + threadIdx.x;
    if (gid < GM) g_invlen[gid] = 1.0f / (float)__ldg(lens + gid);

    const int na8 = GM * GK / 8;
    const int nw8 = GN * GK / 8;
    const int total = na8 + nw8;
    for (int i = gid; i < total; i += gridDim.x * blockDim.x) {
        const float4* src;
        uint4* dst;
        if (i < na8) {
            src = (const float4*)A + (size_t)i * 2;
            dst = (uint4*)g_Ah + i;
        } else {
            src = (const float4*)W + (size_t)(i - na8) * 2;
            dst = (uint4*)g_Wh + (i - na8);
        }
        float4 v0 = __ldg(src);
        float4 v1 = __ldg(src + 1);
        __half2 h0 = __floats2half2_rn(v0.x, v0.y);
        __half2 h1 = __floats2half2_rn(v0.z, v0.w);
        __half2 h2 = __floats2half2_rn(v1.x, v1.y);
        __half2 h3 = __floats2half2_rn(v1.z, v1.w);
        uint4 o4;
        o4.x = *(uint32_t*)&h0;
        o4.y = *(uint32_t*)&h1;
        o4.z = *(uint32_t*)&h2;
        o4.w = *(uint32_t*)&h3;
        *dst = o4;
    }
}

// ───────── stream-K persistent GEMM (fp16 in, fp32 acc) + fused mean-pool ─────────
__global__ void __launch_bounds__(NTHREADS, 1)
gemm_streamk_kernel(const float* __restrict__ phrases, float* __restrict__ out) {
    extern __shared__ char smem[];
    const uint32_t sb = smem_u32(smem);

    const int tid = threadIdx.x;
    const int warp = tid >> 5;
    const int lane = tid & 31;
    const int warp_m = warp & 1;    // 0..1 -> 64-row slab
    const int warp_n = warp >> 1;   // 0..3 -> 32-col slab

    const int c = blockIdx.x;
    const int gs = ctastart(c);
    const int ge = ctastart(c + 1);
    const int n_it = ge - gs;       // 86 or 87
    const int tile0 = gs / ITPT;    // first (possibly partial) tile

    // pooling assignment
    const int prow0 = c * PROWS;
    const int vrows = max(0, min(PROWS, GM - prow0));
    const int msteps = vrows * LL;
    const float4* pf = (const float4*)(phrases + (size_t)prow0 * LL * DD) + tid;

    // per-thread chunk mapping (4 chunks each for A and B per iter)
    int a_off[4];          // element offset within a tile-row-block: row*GK + c8*8
    uint32_t a_dst[4], b_dst[4];
#pragma unroll
    for (int i = 0; i < 4; i++) {
        int id = tid + i * NTHREADS;     // 0..1023
        int row = id >> 3, c8 = id & 7;
        a_off[i] = row * GK + c8 * 8;
        a_dst[i] = row * (APH * 2) + c8 * 16;
        b_dst[i] = A_STAGE_BYTES + row * (APH * 2) + c8 * 16;
    }

    // ldmatrix lane bases
    const int la_row = (lane & 7) + ((lane >> 3) & 1) * 8;
    const uint32_t pA_base = ((warp_m * 64 + la_row) * APH + (lane >> 4) * 8) * 2;
    const int lb_row = (lane & 7) + ((lane >> 4) & 1) * 8;
    const uint32_t pB_base =
        A_STAGE_BYTES + ((warp_n * 32 + lb_row) * APH + ((lane >> 3) & 1) * 8) * 2;

    float acc[4][4][4];
#pragma unroll
    for (int tm = 0; tm < 4; tm++)
#pragma unroll
        for (int tn = 0; tn < 4; tn++)
#pragma unroll
            for (int r = 0; r < 4; r++) acc[tm][tn][r] = 0.0f;

    // preload stages 0..2 (iters gs..gs+2; may cross tile boundary)
#pragma unroll
    for (int s = 0; s < STAGES - 1; s++) {
        const int g = gs + s;
        const int tile = g >> 6, kk = g & 63;
        const __half* ab = g_Ah + (size_t)((tile >> 3) * BM) * GK + kk * BK;
        const __half* bb = g_Wh + (size_t)((tile & 7) * BN) * GK + kk * BK;
        const uint32_t st = sb + (s & 3) * STAGE_BYTES;
#pragma unroll
        for (int i = 0; i < 4; i++) {
            CP_ASYNC16(st + a_dst[i], ab + a_off[i]);
            CP_ASYNC16(st + b_dst[i], bb + a_off[i]);
        }
        CP_COMMIT();
    }

    // pool state: prefetch group 0
    float4 pbuf[PGROUP];
#pragma unroll
    for (int j = 0; j < PGROUP; j++)
        pbuf[j] = (j < msteps) ? __ldg(pf + j * (DD / 4)) : make_float4(0.f, 0.f, 0.f, 0.f);
    float pacc0 = 0.f, pacc1 = 0.f, pacc2 = 0.f, pacc3 = 0.f;
    float pinv = 0.f;
    int parow = 0, ppl = 0;

    uint32_t af[2][4][4], bf[2][4][2];

    for (int i = 0; i < n_it; i++) {
        const int g = gs + i;
        CP_WAIT(STAGES - 2);
        __syncthreads();

        // issue loads for iter i+3
        {
            const int il = i + 3;
            if (il < n_it) {
                const int g3 = gs + il;
                const int tile3 = g3 >> 6, kk3 = g3 & 63;
                const __half* ab = g_Ah + (size_t)((tile3 >> 3) * BM) * GK + kk3 * BK;
                const __half* bb = g_Wh + (size_t)((tile3 & 7) * BN) * GK + kk3 * BK;
                const uint32_t st = sb + (il & 3) * STAGE_BYTES;
#pragma unroll
                for (int j = 0; j < 4; j++) {
                    CP_ASYNC16(st + a_dst[j], ab + a_off[j]);
                    CP_ASYNC16(st + b_dst[j], bb + a_off[j]);
                }
            }
            CP_COMMIT();
        }

        // fused pooling: accumulate group i, prefetch group i+1
        if (i * PGROUP < msteps) {
#pragma unroll
            for (int j = 0; j < PGROUP; j++) {
                if (i * PGROUP + j < msteps) {
                    if (ppl == 0) pinv = __ldg(g_invlen + prow0 + parow);
                    pacc0 += pbuf[j].x; pacc1 += pbuf[j].y;
                    pacc2 += pbuf[j].z; pacc3 += pbuf[j].w;
                    ppl++;
                    if (ppl == LL) {
                        float4 r = make_float4(pacc0 * pinv, pacc1 * pinv,
                                               pacc2 * pinv, pacc3 * pinv);
                        *((float4*)(out + (size_t)(prow0 + parow) * (2 * GN) + GN) + tid) = r;
                        pacc0 = pacc1 = pacc2 = pacc3 = 0.f;
                        ppl = 0;
                        parow++;
                    }
                }
            }
            const int sbase = (i + 1) * PGROUP;
#pragma unroll
            for (int j = 0; j < PGROUP; j++)
                if (sbase + j < msteps) pbuf[j] = __ldg(pf + (sbase + j) * (DD / 4));
        }

        const uint32_t st = sb + (i & 3) * STAGE_BYTES;
        const uint32_t aA = st + pA_base;
        const uint32_t aB = st + pB_base;

        // prefetch fragments for ks=0
#pragma unroll
        for (int tm = 0; tm < 4; tm++)
            LDSM4(af[0][tm][0], af[0][tm][1], af[0][tm][2], af[0][tm][3],
                  aA + (tm * 16 * APH) * 2);
#pragma unroll
        for (int pr = 0; pr < 2; pr++)
            LDSM4(bf[0][pr * 2][0], bf[0][pr * 2][1], bf[0][pr * 2 + 1][0], bf[0][pr * 2 + 1][1],
                  aB + (pr * 16 * APH) * 2);

        // 4 k16-steps, register double-buffered
#pragma unroll
        for (int ks = 0; ks < 4; ks++) {
            const int cur = ks & 1, nxt = cur ^ 1;
            if (ks < 3) {
                const uint32_t ko = (ks + 1) * 32;
#pragma unroll
                for (int tm = 0; tm < 4; tm++)
                    LDSM4(af[nxt][tm][0], af[nxt][tm][1], af[nxt][tm][2], af[nxt][tm][3],
                          aA + (tm * 16 * APH) * 2 + ko);
#pragma unroll
                for (int pr = 0; pr < 2; pr++)
                    LDSM4(bf[nxt][pr * 2][0], bf[nxt][pr * 2][1],
                          bf[nxt][pr * 2 + 1][0], bf[nxt][pr * 2 + 1][1],
                          aB + (pr * 16 * APH) * 2 + ko);
            }
#pragma unroll
            for (int tm = 0; tm < 4; tm++)
#pragma unroll
                for (int tn = 0; tn < 4; tn++)
                    mma_f16(acc[tm][tn][0], acc[tm][tn][1], acc[tm][tn][2], acc[tm][tn][3],
                            af[cur][tm][0], af[cur][tm][1], af[cur][tm][2], af[cur][tm][3],
                            bf[cur][tn][0], bf[cur][tn][1]);
        }

        // flush at tile boundary or range end
        if (((g + 1) & 63) == 0 || i + 1 == n_it) {
            const int tile = g >> 6;
            const int seg = tile - tile0;               // 0..2
            float* pd = g_scr + (size_t)(c * SEGMAX + seg) * (BM * BN);
#pragma unroll
            for (int tn = 0; tn < 4; tn++) {
                const int n = warp_n * 32 + tn * 8 + (lane & 3) * 2;
#pragma unroll
                for (int tm = 0; tm < 4; tm++) {
                    const int r0 = warp_m * 64 + tm * 16 + (lane >> 2);
                    *(float2*)(pd + r0 * BN + n) = make_float2(acc[tm][tn][0], acc[tm][tn][1]);
                    *(float2*)(pd + (r0 + 8) * BN + n) = make_float2(acc[tm][tn][2], acc[tm][tn][3]);
#pragma unroll
                    for (int r = 0; r < 4; r++) acc[tm][tn][r] = 0.0f;
                }
            }
        }
    }
}

// ─────── reduce: per tile, sum <=2 stream-K partials + bias, relu -> out ───────
__global__ void __launch_bounds__(256)
reduce_kernel(const float* __restrict__ bias, float* __restrict__ out) {
    const int t = blockIdx.x;               // 0..199
    const int m0 = (t >> 3) * BM;
    const int n0 = (t & 7) * BN;
    const int tid = threadIdx.x;

    const int c0 = cta_of(t * ITPT);
    const int c1 = cta_of(t * ITPT + ITPT - 1);
    const float* s0 = g_scr + (size_t)(c0 * SEGMAX + (t - ctastart(c0) / ITPT)) * (BM * BN);
    const float* s1 = (c1 != c0)
        ? g_scr + (size_t)(c1 * SEGMAX + (t - ctastart(c1) / ITPT)) * (BM * BN)
        : nullptr;

#pragma unroll
    for (int i = 0; i < 16; i++) {
        const int idx = tid + i * 256;       // 0..4095 float4s
        const int row = idx >> 5, c4 = idx & 31;
        float4 p = *(const float4*)(s0 + row * BN + c4 * 4);
        if (s1) {
            float4 q = *(const float4*)(s1 + row * BN + c4 * 4);
            p.x += q.x; p.y += q.y; p.z += q.z; p.w += q.w;
        }
        float4 bv = __ldg((const float4*)(bias + n0) + c4);
        float4 v;
        v.x = fmaxf(p.x + bv.x, 0.0f);
        v.y = fmaxf(p.y + bv.y, 0.0f);
        v.z = fmaxf(p.z + bv.z, 0.0f);
        v.w = fmaxf(p.w + bv.w, 0.0f);
        *(float4*)(out + (size_t)(m0 + row) * (2 * GN) + n0 + c4 * 4) = v;
    }
}

extern "C" void kernel_launch(void* const* d_in, const int* in_sizes, int n_in,
                              void* d_out, int out_size) {
    const float* features = (const float*)d_in[0];
    const float* phrases  = (const float*)d_in[1];
    const float* W        = (const float*)d_in[2];
    const float* bias     = (const float*)d_in[3];
    const int*   lens     = (const int*)d_in[4];
    float* out = (float*)d_out;

    cvt_f16_kernel<<<2048, 256>>>(features, W, lens);

    cudaFuncSetAttribute(gemm_streamk_kernel, cudaFuncAttributeMaxDynamicSharedMemorySize,
                         SMEM_TOTAL);
    gemm_streamk_kernel<<<NCTA, NTHREADS, SMEM_TOTAL>>>(phrases, out);

    reduce_kernel<<<NTILE, 256>>>(bias, out);
}

// round 12
// speedup vs baseline: 1.0075x; 1.0075x over previous
#include <cuda_runtime.h>
#include <cuda_fp16.h>
#include <cstdint>

// Problem dims
#define BB 64
#define RR 50
#define LL 15
#define DD 1024
#define FF 4096

// GEMM: M=B*R=3200, N=D=1024, K=F=4096
#define GM 3200
#define GN 1024
#define GK 4096

// Stream-K persistent GEMM: 148 CTAs, tile 128x128, BK=64.
#define BM 128
#define BN 128
#define BK 64
#define NTILE_N (GN / BN)            // 8
#define NTILE (GM / BM * NTILE_N)    // 200
#define ITPT (GK / BK)               // 64
#define TOTAL_IT (NTILE * ITPT)      // 12800
#define NCTA 148
#define SEGMAX 3

#define APH 72
#define STAGES 4
#define A_STAGE_BYTES (BM * APH * 2)          // 18432
#define STAGE_BYTES (2 * BM * APH * 2)        // 36864
#define SMEM_TOTAL (STAGES * STAGE_BYTES)     // 147456
#define NTHREADS 256

// pooling fused: 148 CTAs x 22 rows, PGROUP steps/iter
#define PROWS 22
#define PGROUP 4

__device__ __half g_Ah[GM * GK];
__device__ __half g_Wh[GN * GK];
__device__ float g_scr[NCTA * SEGMAX * BM * BN];
__device__ float g_invlen[GM];

__device__ __forceinline__ int ctastart(int c) {
    return (int)(((long long)c * TOTAL_IT) / NCTA);
}
__device__ __forceinline__ int cta_of(int g) {
    int c = (int)(((long long)g * NCTA) / TOTAL_IT);
    while (ctastart(c + 1) <= g) ++c;
    while (ctastart(c) > g) --c;
    return c;
}

__device__ __forceinline__ void mma_f16(float& c0, float& c1, float& c2, float& c3,
                                        uint32_t a0, uint32_t a1, uint32_t a2, uint32_t a3,
                                        uint32_t b0, uint32_t b1) {
    asm volatile(
        "mma.sync.aligned.m16n8k16.row.col.f32.f16.f16.f32 "
        "{%0,%1,%2,%3}, {%4,%5,%6,%7}, {%8,%9}, {%0,%1,%2,%3};\n"
        : "+f"(c0), "+f"(c1), "+f"(c2), "+f"(c3)
        : "r"(a0), "r"(a1), "r"(a2), "r"(a3), "r"(b0), "r"(b1));
}

__device__ __forceinline__ uint32_t smem_u32(const void* p) {
    uint32_t a;
    asm("{ .reg .u64 t; cvta.to.shared.u64 t, %1; cvt.u32.u64 %0, t; }" : "=r"(a) : "l"(p));
    return a;
}

#define CP_ASYNC16(dst, src) \
    asm volatile("cp.async.cg.shared.global [%0], [%1], 16;" :: "r"(dst), "l"(src) : "memory")
#define CP_COMMIT() asm volatile("cp.async.commit_group;" ::: "memory")
#define CP_WAIT(n) asm volatile("cp.async.wait_group %0;" :: "n"(n) : "memory")

#define LDSM4(r0, r1, r2, r3, addr) \
    asm volatile("ldmatrix.sync.aligned.m8n8.x4.shared.b16 {%0,%1,%2,%3}, [%4];" \
                 : "=r"(r0), "=r"(r1), "=r"(r2), "=r"(r3) : "r"(addr))

// ─────────────────── prepass: fp32 -> fp16(rna), plus 1/len ───────────────────
__global__ void __launch_bounds__(256)
cvt_f16_kernel(const float* __restrict__ A, const float* __restrict__ W,
               const int* __restrict__ lens) {
    const int gid = blockIdx.x * blockDim.x + threadIdx.x;
    if (gid < GM) g_invlen[gid] = 1.0f / (float)__ldg(lens + gid);

    const int na8 = GM * GK / 8;
    const int nw8 = GN * GK / 8;
    const int total = na8 + nw8;
    for (int i = gid; i < total; i += gridDim.x * blockDim.x) {
        const float4* src;
        uint4* dst;
        if (i < na8) {
            src = (const float4*)A + (size_t)i * 2;
            dst = (uint4*)g_Ah + i;
        } else {
            src = (const float4*)W + (size_t)(i - na8) * 2;
            dst = (uint4*)g_Wh + (i - na8);
        }
        float4 v0 = __ldg(src);
        float4 v1 = __ldg(src + 1);
        __half2 h0 = __floats2half2_rn(v0.x, v0.y);
        __half2 h1 = __floats2half2_rn(v0.z, v0.w);
        __half2 h2 = __floats2half2_rn(v1.x, v1.y);
        __half2 h3 = __floats2half2_rn(v1.z, v1.w);
        uint4 o4;
        o4.x = *(uint32_t*)&h0;
        o4.y = *(uint32_t*)&h1;
        o4.z = *(uint32_t*)&h2;
        o4.w = *(uint32_t*)&h3;
        *dst = o4;
    }
}

// ───────── stream-K persistent GEMM, phase-static segments, fused mean-pool ─────────
__global__ void __launch_bounds__(NTHREADS, 1)
gemm_streamk_kernel(const float* __restrict__ phrases, float* __restrict__ out) {
    extern __shared__ char smem[];
    const uint32_t sb = smem_u32(smem);

    const int tid = threadIdx.x;
    const int warp = tid >> 5;
    const int lane = tid & 31;
    const int warp_m = warp & 1;
    const int warp_n = warp >> 1;

    const int c = blockIdx.x;
    const int gs = ctastart(c);
    const int ge = ctastart(c + 1);

    // pooling assignment
    const int prow0 = c * PROWS;
    const int vrows = max(0, min(PROWS, GM - prow0));
    const int msteps = vrows * LL;
    const float4* pf = (const float4*)(phrases + (size_t)prow0 * LL * DD) + tid;

    // per-thread chunk mapping
    int a_off[4];
    uint32_t a_dst[4], b_dst[4];
#pragma unroll
    for (int i = 0; i < 4; i++) {
        int id = tid + i * NTHREADS;
        int row = id >> 3, c8 = id & 7;
        a_off[i] = row * GK + c8 * 8;
        a_dst[i] = row * (APH * 2) + c8 * 16;
        b_dst[i] = A_STAGE_BYTES + row * (APH * 2) + c8 * 16;
    }

    const int la_row = (lane & 7) + ((lane >> 3) & 1) * 8;
    const uint32_t pA_base = ((warp_m * 64 + la_row) * APH + (lane >> 4) * 8) * 2;
    const int lb_row = (lane & 7) + ((lane >> 4) & 1) * 8;
    const uint32_t pB_base =
        A_STAGE_BYTES + ((warp_n * 32 + lb_row) * APH + ((lane >> 3) & 1) * 8) * 2;

    float acc[4][4][4];
#pragma unroll
    for (int tm = 0; tm < 4; tm++)
#pragma unroll
        for (int tn = 0; tn < 4; tn++)
#pragma unroll
            for (int r = 0; r < 4; r++) acc[tm][tn][r] = 0.0f;

    // pool state
    float4 pbuf[PGROUP];
#pragma unroll
    for (int j = 0; j < PGROUP; j++)
        pbuf[j] = (j < msteps) ? __ldg(pf + j * (DD / 4)) : make_float4(0.f, 0.f, 0.f, 0.f);
    float pacc0 = 0.f, pacc1 = 0.f, pacc2 = 0.f, pacc3 = 0.f;
    float pinv = 0.f;
    int parow = 0, ppl = 0, pit = 0;

    uint32_t af[2][4][4], bf[2][4][2];

#define POOL_STEP() do {                                                          \
    if (pit * PGROUP < msteps) {                                                  \
        _Pragma("unroll")                                                         \
        for (int _j = 0; _j < PGROUP; _j++) {                                     \
            if (pit * PGROUP + _j < msteps) {                                     \
                if (ppl == 0) pinv = __ldg(g_invlen + prow0 + parow);             \
                pacc0 += pbuf[_j].x; pacc1 += pbuf[_j].y;                         \
                pacc2 += pbuf[_j].z; pacc3 += pbuf[_j].w;                         \
                ppl++;                                                            \
                if (ppl == LL) {                                                  \
                    float4 _r = make_float4(pacc0 * pinv, pacc1 * pinv,           \
                                            pacc2 * pinv, pacc3 * pinv);          \
                    *((float4*)(out + (size_t)(prow0 + parow) * (2 * GN) + GN) + tid) = _r; \
                    pacc0 = pacc1 = pacc2 = pacc3 = 0.f;                          \
                    ppl = 0; parow++;                                             \
                }                                                                 \
            }                                                                     \
        }                                                                         \
        const int _s2 = (pit + 1) * PGROUP;                                       \
        _Pragma("unroll")                                                         \
        for (int _j = 0; _j < PGROUP; _j++)                                       \
            if (_s2 + _j < msteps) pbuf[_j] = __ldg(pf + (_s2 + _j) * (DD / 4));  \
    }                                                                             \
    pit++;                                                                        \
} while (0)

#define GEMM_ITER(PH) do {                                                        \
    CP_WAIT(STAGES - 2);                                                          \
    __syncthreads();                                                              \
    {                                                                             \
        const int _jl = j + 3;                                                    \
        if (_jl < run) {                                                          \
            const uint32_t _st = sb + (((PH) + 3) & 3) * STAGE_BYTES;             \
            const __half* _as = aseg + _jl * BK;                                  \
            const __half* _bs = bseg + _jl * BK;                                  \
            _Pragma("unroll")                                                     \
            for (int _i = 0; _i < 4; _i++) {                                      \
                CP_ASYNC16(_st + a_dst[_i], _as + a_off[_i]);                     \
                CP_ASYNC16(_st + b_dst[_i], _bs + a_off[_i]);                     \
            }                                                                     \
        }                                                                         \
        CP_COMMIT();                                                              \
    }                                                                             \
    POOL_STEP();                                                                  \
    {                                                                             \
        const uint32_t _aA = sb + (PH) * STAGE_BYTES + pA_base;                   \
        const uint32_t _aB = sb + (PH) * STAGE_BYTES + pB_base;                   \
        _Pragma("unroll")                                                         \
        for (int tm = 0; tm < 4; tm++)                                            \
            LDSM4(af[0][tm][0], af[0][tm][1], af[0][tm][2], af[0][tm][3],         \
                  _aA + (tm * 16 * APH) * 2);                                     \
        _Pragma("unroll")                                                         \
        for (int pr = 0; pr < 2; pr++)                                            \
            LDSM4(bf[0][pr * 2][0], bf[0][pr * 2][1],                             \
                  bf[0][pr * 2 + 1][0], bf[0][pr * 2 + 1][1],                     \
                  _aB + (pr * 16 * APH) * 2);                                     \
        _Pragma("unroll")                                                         \
        for (int ks = 0; ks < 4; ks++) {                                          \
            const int cur = ks & 1, nxt = cur ^ 1;                                \
            if (ks < 3) {                                                         \
                const uint32_t ko = (ks + 1) * 32;                                \
                _Pragma("unroll")                                                 \
                for (int tm = 0; tm < 4; tm++)                                    \
                    LDSM4(af[nxt][tm][0], af[nxt][tm][1], af[nxt][tm][2],         \
                          af[nxt][tm][3], _aA + (tm * 16 * APH) * 2 + ko);        \
                _Pragma("unroll")                                                 \
                for (int pr = 0; pr < 2; pr++)                                    \
                    LDSM4(bf[nxt][pr * 2][0], bf[nxt][pr * 2][1],                 \
                          bf[nxt][pr * 2 + 1][0], bf[nxt][pr * 2 + 1][1],         \
                          _aB + (pr * 16 * APH) * 2 + ko);                        \
            }                                                                     \
            _Pragma("unroll")                                                     \
            for (int tm = 0; tm < 4; tm++)                                        \
                _Pragma("unroll")                                                 \
                for (int tn = 0; tn < 4; tn++)                                    \
                    mma_f16(acc[tm][tn][0], acc[tm][tn][1], acc[tm][tn][2],       \
                            acc[tm][tn][3],                                       \
                            af[cur][tm][0], af[cur][tm][1], af[cur][tm][2],       \
                            af[cur][tm][3], bf[cur][tn][0], bf[cur][tn][1]);      \
        }                                                                         \
    }                                                                             \
    j++;                                                                          \
} while (0)

    int g = gs;
    int seg = 0;
    while (g < ge) {
        const int tile = g >> 6;
        const int kk0 = g & 63;
        const int rem = ge - g;
        const int run = min(rem, ITPT - kk0);

        const __half* aseg = g_Ah + (size_t)((tile >> 3) * BM) * GK + kk0 * BK;
        const __half* bseg = g_Wh + (size_t)((tile & 7) * BN) * GK + kk0 * BK;

        __syncthreads();   // protect smem reuse across segments

        // preload iters 0..2 of this segment into stages 0..2
#pragma unroll
        for (int s = 0; s < STAGES - 1; s++) {
            if (s < run) {
                const uint32_t st = sb + s * STAGE_BYTES;
                const __half* as = aseg + s * BK;
                const __half* bs = bseg + s * BK;
#pragma unroll
                for (int i = 0; i < 4; i++) {
                    CP_ASYNC16(st + a_dst[i], as + a_off[i]);
                    CP_ASYNC16(st + b_dst[i], bs + a_off[i]);
                }
            }
            CP_COMMIT();
        }

        int j = 0;
        while (j + 4 <= run) {
            GEMM_ITER(0);
            GEMM_ITER(1);
            GEMM_ITER(2);
            GEMM_ITER(3);
        }
        if (j < run) GEMM_ITER(0);
        if (j < run) GEMM_ITER(1);
        if (j < run) GEMM_ITER(2);

        // flush partial for this tile segment, zero accumulators
        {
            float* pd = g_scr + (size_t)(c * SEGMAX + seg) * (BM * BN);
#pragma unroll
            for (int tn = 0; tn < 4; tn++) {
                const int n = warp_n * 32 + tn * 8 + (lane & 3) * 2;
#pragma unroll
                for (int tm = 0; tm < 4; tm++) {
                    const int r0 = warp_m * 64 + tm * 16 + (lane >> 2);
                    *(float2*)(pd + r0 * BN + n) = make_float2(acc[tm][tn][0], acc[tm][tn][1]);
                    *(float2*)(pd + (r0 + 8) * BN + n) =
                        make_float2(acc[tm][tn][2], acc[tm][tn][3]);
#pragma unroll
                    for (int r = 0; r < 4; r++) acc[tm][tn][r] = 0.0f;
                }
            }
        }
        seg++;
        g += run;
    }
#undef GEMM_ITER
#undef POOL_STEP
}

// ─────── reduce: per tile, sum <=2 stream-K partials (ascending k) + bias + relu ───────
__global__ void __launch_bounds__(256)
reduce_kernel(const float* __restrict__ bias, float* __restrict__ out) {
    const int t = blockIdx.x;               // 0..199
    const int m0 = (t >> 3) * BM;
    const int n0 = (t & 7) * BN;
    const int tid = threadIdx.x;

    const int c0 = cta_of(t * ITPT);
    const int c1 = cta_of(t * ITPT + ITPT - 1);
    const float* s0 = g_scr + (size_t)(c0 * SEGMAX + (t - ctastart(c0) / ITPT)) * (BM * BN);
    const float* s1 = (c1 != c0)
        ? g_scr + (size_t)(c1 * SEGMAX + (t - ctastart(c1) / ITPT)) * (BM * BN)
        : nullptr;

#pragma unroll
    for (int i = 0; i < 16; i++) {
        const int idx = tid + i * 256;
        const int row = idx >> 5, c4 = idx & 31;
        float4 p = *(const float4*)(s0 + row * BN + c4 * 4);
        if (s1) {
            float4 q = *(const float4*)(s1 + row * BN + c4 * 4);
            p.x += q.x; p.y += q.y; p.z += q.z; p.w += q.w;
        }
        float4 bv = __ldg((const float4*)(bias + n0) + c4);
        float4 v;
        v.x = fmaxf(p.x + bv.x, 0.0f);
        v.y = fmaxf(p.y + bv.y, 0.0f);
        v.z = fmaxf(p.z + bv.z, 0.0f);
        v.w = fmaxf(p.w + bv.w, 0.0f);
        *(float4*)(out + (size_t)(m0 + row) * (2 * GN) + n0 + c4 * 4) = v;
    }
}

extern "C" void kernel_launch(void* const* d_in, const int* in_sizes, int n_in,
                              void* d_out, int out_size) {
    const float* features = (const float*)d_in[0];
    const float* phrases  = (const float*)d_in[1];
    const float* W        = (const float*)d_in[2];
    const float* bias     = (const float*)d_in[3];
    const int*   lens     = (const int*)d_in[4];
    float* out = (float*)d_out;

    cvt_f16_kernel<<<2048, 256>>>(features, W, lens);

    cudaFuncSetAttribute(gemm_streamk_kernel, cudaFuncAttributeMaxDynamicSharedMemorySize,
                         SMEM_TOTAL);
    gemm_streamk_kernel<<<NCTA, NTHREADS, SMEM_TOTAL>>>(phrases, out);

    reduce_kernel<<<NTILE, 256>>>(bias, out);
}

// round 13
// speedup vs baseline: 1.0620x; 1.0541x over previous
#include <cuda_runtime.h>
#include <cuda_fp16.h>
#include <cstdint>

// Problem dims
#define BB 64
#define RR 50
#define LL 15
#define DD 1024
#define FF 4096

// GEMM: M=B*R=3200, N=D=1024, K=F=4096
#define GM 3200
#define GN 1024
#define GK 4096

#define BM 128
#define BN 128
#define BK 64
#define NTILE 200            // 25 x 8
#define NFULL 148            // tiles 0..147: full-K blocks (one wave)
#define NTAIL (NTILE - NFULL)   // 52 tiles
#define TSPLIT 4             // tail split-K
#define NTAILCTA (NTAIL * TSPLIT)  // 208
#define NGRID (NFULL + NTAILCTA)   // 356

#define APH 72               // padded row stride in halves (144B, conflict-free)
#define STAGES 4
#define A_STAGE_BYTES (BM * APH * 2)          // 18432
#define STAGE_BYTES (2 * BM * APH * 2)        // 36864
#define SMEM_TOTAL (STAGES * STAGE_BYTES)     // 147456
#define NTHREADS 256

// pooling fused into the 148 full blocks: 22 rows each, 6 steps/iter
#define PROWS 22
#define PGROUP 6

__device__ __half g_Ah[GM * GK];
__device__ __half g_Wh[GN * GK];
__device__ float g_scr[NTAILCTA * BM * BN];   // 13.9 MB tail partials
__device__ float g_invlen[GM];

__device__ __forceinline__ void mma_f16(float& c0, float& c1, float& c2, float& c3,
                                        uint32_t a0, uint32_t a1, uint32_t a2, uint32_t a3,
                                        uint32_t b0, uint32_t b1) {
    asm volatile(
        "mma.sync.aligned.m16n8k16.row.col.f32.f16.f16.f32 "
        "{%0,%1,%2,%3}, {%4,%5,%6,%7}, {%8,%9}, {%0,%1,%2,%3};\n"
        : "+f"(c0), "+f"(c1), "+f"(c2), "+f"(c3)
        : "r"(a0), "r"(a1), "r"(a2), "r"(a3), "r"(b0), "r"(b1));
}

__device__ __forceinline__ uint32_t smem_u32(const void* p) {
    uint32_t a;
    asm("{ .reg .u64 t; cvta.to.shared.u64 t, %1; cvt.u32.u64 %0, t; }" : "=r"(a) : "l"(p));
    return a;
}

#define CP_ASYNC16(dst, src) \
    asm volatile("cp.async.cg.shared.global [%0], [%1], 16;" :: "r"(dst), "l"(src) : "memory")
#define CP_COMMIT() asm volatile("cp.async.commit_group;" ::: "memory")
#define CP_WAIT(n) asm volatile("cp.async.wait_group %0;" :: "n"(n) : "memory")

#define LDSM4(r0, r1, r2, r3, addr) \
    asm volatile("ldmatrix.sync.aligned.m8n8.x4.shared.b16 {%0,%1,%2,%3}, [%4];" \
                 : "=r"(r0), "=r"(r1), "=r"(r2), "=r"(r3) : "r"(addr))

// ─────────────────── prepass: fp32 -> fp16(rna), plus 1/len ───────────────────
__global__ void __launch_bounds__(256)
cvt_f16_kernel(const float* __restrict__ A, const float* __restrict__ W,
               const int* __restrict__ lens) {
    const int gid = blockIdx.x * blockDim.x + threadIdx.x;
    if (gid < GM) g_invlen[gid] = 1.0f / (float)__ldg(lens + gid);

    const int na8 = GM * GK / 8;
    const int nw8 = GN * GK / 8;
    const int total = na8 + nw8;
    for (int i = gid; i < total; i += gridDim.x * blockDim.x) {
        const float4* src;
        uint4* dst;
        if (i < na8) {
            src = (const float4*)A + (size_t)i * 2;
            dst = (uint4*)g_Ah + i;
        } else {
            src = (const float4*)W + (size_t)(i - na8) * 2;
            dst = (uint4*)g_Wh + (i - na8);
        }
        float4 v0 = __ldg(src);
        float4 v1 = __ldg(src + 1);
        __half2 h0 = __floats2half2_rn(v0.x, v0.y);
        __half2 h1 = __floats2half2_rn(v0.z, v0.w);
        __half2 h2 = __floats2half2_rn(v1.x, v1.y);
        __half2 h3 = __floats2half2_rn(v1.z, v1.w);
        uint4 o4;
        o4.x = *(uint32_t*)&h0;
        o4.y = *(uint32_t*)&h1;
        o4.z = *(uint32_t*)&h2;
        o4.w = *(uint32_t*)&h3;
        *dst = o4;
    }
}

// ───────── shared tile body: FULL (K=4096, pool, direct epilogue) or TAIL ─────────
template <int NIT, bool FULL>
__device__ __forceinline__ void tile_body(
    const float* __restrict__ phrases, const float* __restrict__ bias,
    float* __restrict__ out, float* __restrict__ scr,
    int m0, int n0, int kbase, int prow0, char* smem) {
    const uint32_t sb = smem_u32(smem);
    const int tid = threadIdx.x;
    const int warp = tid >> 5;
    const int lane = tid & 31;
    const int warp_m = warp & 1;
    const int warp_n = warp >> 1;

    // pool setup (FULL only)
    const int vrows = FULL ? max(0, min(PROWS, GM - prow0)) : 0;
    const int msteps = vrows * LL;
    const float4* pf = (const float4*)(phrases + (size_t)prow0 * LL * DD) + tid;

    uint32_t a_dst[4], b_dst[4];
    const __half* a_src[4];
    const __half* b_src[4];
#pragma unroll
    for (int i = 0; i < 4; i++) {
        int id = tid + i * NTHREADS;
        int row = id >> 3, c8 = id & 7;
        a_dst[i] = row * (APH * 2) + c8 * 16;
        b_dst[i] = A_STAGE_BYTES + row * (APH * 2) + c8 * 16;
        a_src[i] = g_Ah + (size_t)(m0 + row) * GK + kbase + c8 * 8;
        b_src[i] = g_Wh + (size_t)(n0 + row) * GK + kbase + c8 * 8;
    }

    const int la_row = (lane & 7) + ((lane >> 3) & 1) * 8;
    const uint32_t pA_base = ((warp_m * 64 + la_row) * APH + (lane >> 4) * 8) * 2;
    const int lb_row = (lane & 7) + ((lane >> 4) & 1) * 8;
    const uint32_t pB_base =
        A_STAGE_BYTES + ((warp_n * 32 + lb_row) * APH + ((lane >> 3) & 1) * 8) * 2;

    float acc[4][4][4];
#pragma unroll
    for (int tm = 0; tm < 4; tm++)
#pragma unroll
        for (int tn = 0; tn < 4; tn++)
#pragma unroll
            for (int r = 0; r < 4; r++) acc[tm][tn][r] = 0.0f;

#pragma unroll
    for (int s = 0; s < STAGES - 1; s++) {
        const uint32_t st = sb + s * STAGE_BYTES;
        const int k0 = s * BK;
#pragma unroll
        for (int i = 0; i < 4; i++) {
            CP_ASYNC16(st + a_dst[i], a_src[i] + k0);
            CP_ASYNC16(st + b_dst[i], b_src[i] + k0);
        }
        CP_COMMIT();
    }

    // pool state
    float4 pbuf[PGROUP];
    if (FULL) {
#pragma unroll
        for (int j = 0; j < PGROUP; j++)
            pbuf[j] = (j < msteps) ? __ldg(pf + j * (DD / 4)) : make_float4(0.f, 0.f, 0.f, 0.f);
    }
    float pacc0 = 0.f, pacc1 = 0.f, pacc2 = 0.f, pacc3 = 0.f;
    float pinv = 0.f;
    int parow = 0, ppl = 0;

    uint32_t af[2][4][4], bf[2][4][2];

#pragma unroll 4
    for (int it = 0; it < NIT; it++) {
        CP_WAIT(STAGES - 2);
        __syncthreads();

        {
            const int ld = it + STAGES - 1;
            if (ld < NIT) {
                const uint32_t st = sb + (ld & (STAGES - 1)) * STAGE_BYTES;
                const int k0 = ld * BK;
#pragma unroll
                for (int i = 0; i < 4; i++) {
                    CP_ASYNC16(st + a_dst[i], a_src[i] + k0);
                    CP_ASYNC16(st + b_dst[i], b_src[i] + k0);
                }
            }
            CP_COMMIT();
        }

        if (FULL && it * PGROUP < msteps) {
#pragma unroll
            for (int j = 0; j < PGROUP; j++) {
                if (it * PGROUP + j < msteps) {
                    if (ppl == 0) pinv = __ldg(g_invlen + prow0 + parow);
                    pacc0 += pbuf[j].x; pacc1 += pbuf[j].y;
                    pacc2 += pbuf[j].z; pacc3 += pbuf[j].w;
                    ppl++;
                    if (ppl == LL) {
                        float4 r = make_float4(pacc0 * pinv, pacc1 * pinv,
                                               pacc2 * pinv, pacc3 * pinv);
                        *((float4*)(out + (size_t)(prow0 + parow) * (2 * GN) + GN) + tid) = r;
                        pacc0 = pacc1 = pacc2 = pacc3 = 0.f;
                        ppl = 0;
                        parow++;
                    }
                }
            }
            const int sbase = (it + 1) * PGROUP;
#pragma unroll
            for (int j = 0; j < PGROUP; j++)
                if (sbase + j < msteps) pbuf[j] = __ldg(pf + (sbase + j) * (DD / 4));
        }

        const uint32_t st = sb + (it & (STAGES - 1)) * STAGE_BYTES;
        const uint32_t aA = st + pA_base;
        const uint32_t aB = st + pB_base;

#pragma unroll
        for (int tm = 0; tm < 4; tm++)
            LDSM4(af[0][tm][0], af[0][tm][1], af[0][tm][2], af[0][tm][3],
                  aA + (tm * 16 * APH) * 2);
#pragma unroll
        for (int pr = 0; pr < 2; pr++)
            LDSM4(bf[0][pr * 2][0], bf[0][pr * 2][1], bf[0][pr * 2 + 1][0], bf[0][pr * 2 + 1][1],
                  aB + (pr * 16 * APH) * 2);

#pragma unroll
        for (int ks = 0; ks < 4; ks++) {
            const int cur = ks & 1, nxt = cur ^ 1;
            if (ks < 3) {
                const uint32_t ko = (ks + 1) * 32;
#pragma unroll
                for (int tm = 0; tm < 4; tm++)
                    LDSM4(af[nxt][tm][0], af[nxt][tm][1], af[nxt][tm][2], af[nxt][tm][3],
                          aA + (tm * 16 * APH) * 2 + ko);
#pragma unroll
                for (int pr = 0; pr < 2; pr++)
                    LDSM4(bf[nxt][pr * 2][0], bf[nxt][pr * 2][1],
                          bf[nxt][pr * 2 + 1][0], bf[nxt][pr * 2 + 1][1],
                          aB + (pr * 16 * APH) * 2 + ko);
            }
#pragma unroll
            for (int tm = 0; tm < 4; tm++)
#pragma unroll
                for (int tn = 0; tn < 4; tn++)
                    mma_f16(acc[tm][tn][0], acc[tm][tn][1], acc[tm][tn][2], acc[tm][tn][3],
                            af[cur][tm][0], af[cur][tm][1], af[cur][tm][2], af[cur][tm][3],
                            bf[cur][tn][0], bf[cur][tn][1]);
        }
    }

    if (FULL) {
        // direct epilogue: relu(acc + bias) -> out[:, 0:1024]
#pragma unroll
        for (int tn = 0; tn < 4; tn++) {
            const int n = n0 + warp_n * 32 + tn * 8 + (lane & 3) * 2;
            const float b0 = __ldg(bias + n);
            const float b1 = __ldg(bias + n + 1);
#pragma unroll
            for (int tm = 0; tm < 4; tm++) {
                const int r0 = m0 + warp_m * 64 + tm * 16 + (lane >> 2);
                float2 v0, v1;
                v0.x = fmaxf(acc[tm][tn][0] + b0, 0.0f);
                v0.y = fmaxf(acc[tm][tn][1] + b1, 0.0f);
                v1.x = fmaxf(acc[tm][tn][2] + b0, 0.0f);
                v1.y = fmaxf(acc[tm][tn][3] + b1, 0.0f);
                *(float2*)(out + (size_t)r0 * (2 * GN) + n) = v0;
                *(float2*)(out + (size_t)(r0 + 8) * (2 * GN) + n) = v1;
            }
        }
    } else {
        // tail: raw partial to scratch
#pragma unroll
        for (int tn = 0; tn < 4; tn++) {
            const int n = warp_n * 32 + tn * 8 + (lane & 3) * 2;
#pragma unroll
            for (int tm = 0; tm < 4; tm++) {
                const int r0 = warp_m * 64 + tm * 16 + (lane >> 2);
                *(float2*)(scr + r0 * BN + n) = make_float2(acc[tm][tn][0], acc[tm][tn][1]);
                *(float2*)(scr + (r0 + 8) * BN + n) = make_float2(acc[tm][tn][2], acc[tm][tn][3]);
            }
        }
    }
}

__global__ void __launch_bounds__(NTHREADS, 1)
gemm_hybrid_kernel(const float* __restrict__ phrases, const float* __restrict__ bias,
                   float* __restrict__ out) {
    extern __shared__ char smem[];
    const int bid = blockIdx.x;
    if (bid < NFULL) {
        const int m0 = (bid >> 3) * BM;
        const int n0 = (bid & 7) * BN;
        tile_body<GK / BK, true>(phrases, bias, out, nullptr, m0, n0, 0, bid * PROWS, smem);
    } else {
        const int tb = bid - NFULL;             // 0..207
        const int t = NFULL + (tb >> 2);        // tile 148..199
        const int s = tb & 3;                   // split 0..3
        tile_body<GK / BK / TSPLIT, false>(phrases, bias, out,
                                           g_scr + (size_t)tb * (BM * BN),
                                           (t >> 3) * BM, (t & 7) * BN,
                                           s * (GK / TSPLIT), 0, smem);
    }
}

// ───── reduce (tail tiles only): sum 4 partials (ascending k) + bias + relu ─────
__global__ void __launch_bounds__(256)
reduce_tail_kernel(const float* __restrict__ bias, float* __restrict__ out) {
    const int r = blockIdx.x;               // 0..51
    const int t = NFULL + r;
    const int m0 = (t >> 3) * BM;
    const int n0 = (t & 7) * BN;
    const int tid = threadIdx.x;
    const float* s0 = g_scr + (size_t)(r * 4 + 0) * (BM * BN);
    const float* s1 = g_scr + (size_t)(r * 4 + 1) * (BM * BN);
    const float* s2 = g_scr + (size_t)(r * 4 + 2) * (BM * BN);
    const float* s3 = g_scr + (size_t)(r * 4 + 3) * (BM * BN);

#pragma unroll
    for (int i = 0; i < 16; i++) {
        const int idx = tid + i * 256;
        const int row = idx >> 5, c4 = idx & 31;
        const int o = row * BN + c4 * 4;
        float4 p = *(const float4*)(s0 + o);
        float4 q1 = *(const float4*)(s1 + o);
        float4 q2 = *(const float4*)(s2 + o);
        float4 q3 = *(const float4*)(s3 + o);
        p.x = ((p.x + q1.x) + q2.x) + q3.x;
        p.y = ((p.y + q1.y) + q2.y) + q3.y;
        p.z = ((p.z + q1.z) + q2.z) + q3.z;
        p.w = ((p.w + q1.w) + q2.w) + q3.w;
        float4 bv = __ldg((const float4*)(bias + n0) + c4);
        float4 v;
        v.x = fmaxf(p.x + bv.x, 0.0f);
        v.y = fmaxf(p.y + bv.y, 0.0f);
        v.z = fmaxf(p.z + bv.z, 0.0f);
        v.w = fmaxf(p.w + bv.w, 0.0f);
        *(float4*)(out + (size_t)(m0 + row) * (2 * GN) + n0 + c4 * 4) = v;
    }
}

extern "C" void kernel_launch(void* const* d_in, const int* in_sizes, int n_in,
                              void* d_out, int out_size) {
    const float* features = (const float*)d_in[0];
    const float* phrases  = (const float*)d_in[1];
    const float* W        = (const float*)d_in[2];
    const float* bias     = (const float*)d_in[3];
    const int*   lens     = (const int*)d_in[4];
    float* out = (float*)d_out;

    cvt_f16_kernel<<<2048, 256>>>(features, W, lens);

    cudaFuncSetAttribute(gemm_hybrid_kernel, cudaFuncAttributeMaxDynamicSharedMemorySize,
                         SMEM_TOTAL);
    gemm_hybrid_kernel<<<NGRID, NTHREADS, SMEM_TOTAL>>>(phrases, bias, out);

    reduce_tail_kernel<<<NTAIL, 256>>>(bias, out);
}